// round 1
// baseline (speedup 1.0000x reference)
#include <cuda_runtime.h>
#include <cstdint>

#define NR 13824
#define ND 1728
#define EDIM 512
#define FDIM 512      // feature layout: [0,256) repr | [256,384) con | [384,512) off
#define OUTC 64

#define SM_SCALE 0.25f                       // 1/(sqrt(256)*0.25)
#define INV_SQRT_H 0.088388347648318447f     // 1/sqrt(128)
#define MAX_CONTRAST 1.8f

// Scratch (static __device__ arrays: allocation-guard safe)
__device__ float g_rfeat[(size_t)NR * FDIM];
__device__ float g_dfeat[(size_t)ND * FDIM];

// ---------------------------------------------------------------------------
// Projection GEMM: out[m, col_off + n] = sum_k (L+P)[m,k] * W[k,n] + bias[n]
// Tile 64x64, 256 threads, 4x4 register frags.
// ---------------------------------------------------------------------------
__global__ __launch_bounds__(256) void proj_kernel(
    const float* __restrict__ L, const float* __restrict__ P,
    const float* __restrict__ W, const float* __restrict__ bias,
    int N, int col_off, int which)
{
    __shared__ float As[16][68];   // [k][m], padded for banks + 16B align
    __shared__ float Bs[16][64];   // [k][n]
    float* out = which ? g_dfeat : g_rfeat;

    const int tid = threadIdx.x;
    const int tx = tid & 15, ty = tid >> 4;
    const int m0 = blockIdx.y * 64;
    const int n0 = blockIdx.x * 64;

    const int lk  = tid & 15;   // A-load k
    const int lm  = tid >> 4;   // A-load m base
    const int ln  = tid & 63;   // B-load n
    const int lkb = tid >> 6;   // B-load k base

    float acc[4][4] = {};

    for (int k0 = 0; k0 < EDIM; k0 += 16) {
        __syncthreads();
#pragma unroll
        for (int p = 0; p < 4; p++) {
            int row = m0 + lm + p * 16;
            As[lk][lm + p * 16] =
                L[(size_t)row * EDIM + k0 + lk] + P[(size_t)row * EDIM + k0 + lk];
        }
#pragma unroll
        for (int p = 0; p < 4; p++)
            Bs[lkb + p * 4][ln] = W[(size_t)(k0 + lkb + p * 4) * N + n0 + ln];
        __syncthreads();
#pragma unroll
        for (int kk = 0; kk < 16; kk++) {
            float4 a4 = *(const float4*)&As[kk][4 * ty];
            float4 b4 = *(const float4*)&Bs[kk][4 * tx];
            float av[4] = {a4.x, a4.y, a4.z, a4.w};
            float bv[4] = {b4.x, b4.y, b4.z, b4.w};
#pragma unroll
            for (int i = 0; i < 4; i++)
#pragma unroll
                for (int j = 0; j < 4; j++)
                    acc[i][j] = fmaf(av[i], bv[j], acc[i][j]);
        }
    }
#pragma unroll
    for (int i = 0; i < 4; i++)
#pragma unroll
        for (int j = 0; j < 4; j++) {
            int col = n0 + 4 * tx + j;
            out[(size_t)(m0 + 4 * ty + i) * FDIM + col_off + col] =
                acc[i][j] + bias[col];
        }
}

// ---------------------------------------------------------------------------
// Fused attention: per 64-row range tile, online softmax over all 1728 domains.
// ---------------------------------------------------------------------------
__device__ __forceinline__ void attn_gemm(
    float (&s)[4][4],
    const float* __restrict__ Qbase, const float* __restrict__ Kbase,
    int kbeg, int kend,
    float (*Qs)[68], float (*Ks)[68],
    int tid, int tx, int ty)
{
    const int lk = tid & 15;
    const int lm = tid >> 4;
    for (int k0 = kbeg; k0 < kend; k0 += 16) {
        __syncthreads();
#pragma unroll
        for (int p = 0; p < 4; p++) {
            Qs[lk][lm + p * 16] = Qbase[(size_t)(lm + p * 16) * FDIM + k0 + lk];
            Ks[lk][lm + p * 16] = Kbase[(size_t)(lm + p * 16) * FDIM + k0 + lk];
        }
        __syncthreads();
#pragma unroll
        for (int kk = 0; kk < 16; kk++) {
            float4 a4 = *(const float4*)&Qs[kk][4 * ty];
            float4 b4 = *(const float4*)&Ks[kk][4 * tx];
            float av[4] = {a4.x, a4.y, a4.z, a4.w};
            float bv[4] = {b4.x, b4.y, b4.z, b4.w};
#pragma unroll
            for (int i = 0; i < 4; i++)
#pragma unroll
                for (int j = 0; j < 4; j++)
                    s[i][j] = fmaf(av[i], bv[j], s[i][j]);
        }
    }
}

__global__ __launch_bounds__(256, 2) void attn_kernel(
    const float* __restrict__ Vmat,   // pooled_domains [ND][64]
    float* __restrict__ out)          // [NR][64]
{
    __shared__ float Qs[16][68];
    __shared__ float Ks[16][68];
    __shared__ float PCs[64][68];     // p * contrast, padded
    __shared__ float Vs[64][64];

    const int tid = threadIdx.x;
    const int tx = tid & 15, ty = tid >> 4;
    const int r0 = blockIdx.x * 64;
    const float* Qbase = g_rfeat + (size_t)r0 * FDIM;

    float acc[4][4] = {};
    float m_i[4], l_part[4] = {}, off_part[4] = {};
#pragma unroll
    for (int i = 0; i < 4; i++) m_i[i] = -3.0e38f;

    for (int d0 = 0; d0 < ND; d0 += 64) {
        const float* Kbase = g_dfeat + (size_t)d0 * FDIM;
        float s_repr[4][4] = {};
        float s_con[4][4]  = {};
        float s_off[4][4]  = {};
        attn_gemm(s_repr, Qbase, Kbase,   0, 256, Qs, Ks, tid, tx, ty);
        attn_gemm(s_con,  Qbase, Kbase, 256, 384, Qs, Ks, tid, tx, ty);
        attn_gemm(s_off,  Qbase, Kbase, 384, 512, Qs, Ks, tid, tx, ty);

        float alpha[4];
        float pc[4][4];
#pragma unroll
        for (int i = 0; i < 4; i++) {
            float mx = -3.0e38f;
#pragma unroll
            for (int j = 0; j < 4; j++) {
                float lg = s_repr[i][j] * SM_SCALE;
                s_repr[i][j] = lg;
                mx = fmaxf(mx, lg);
            }
#pragma unroll
            for (int d = 1; d < 16; d <<= 1)
                mx = fmaxf(mx, __shfl_xor_sync(0xffffffffu, mx, d));
            float m_new = fmaxf(m_i[i], mx);
            alpha[i] = __expf(m_i[i] - m_new);
            m_i[i] = m_new;
            float lsum = 0.f, osum = 0.f;
#pragma unroll
            for (int j = 0; j < 4; j++) {
                float p = __expf(s_repr[i][j] - m_new);
                float c = tanhf(s_con[i][j] * INV_SQRT_H) * MAX_CONTRAST;
                float o = tanhf(s_off[i][j] * INV_SQRT_H);
                lsum += p;
                osum = fmaf(p, o, osum);
                pc[i][j] = p * c;
            }
            l_part[i]   = fmaf(l_part[i],   alpha[i], lsum);
            off_part[i] = fmaf(off_part[i], alpha[i], osum);
        }

        // Stage p*contrast and V tile to smem
#pragma unroll
        for (int i = 0; i < 4; i++)
            *(float4*)&PCs[4 * ty + i][4 * tx] =
                make_float4(pc[i][0], pc[i][1], pc[i][2], pc[i][3]);
        {
            const int c = tid & 63;
            const int rb = tid >> 6;
#pragma unroll
            for (int p = 0; p < 16; p++)
                Vs[rb + p * 4][c] = Vmat[(size_t)(d0 + rb + p * 4) * OUTC + c];
        }
        __syncthreads();

        // acc = acc*alpha + PC @ V  (64x64x64)
#pragma unroll
        for (int i = 0; i < 4; i++)
#pragma unroll
            for (int j = 0; j < 4; j++)
                acc[i][j] *= alpha[i];
        for (int k = 0; k < 64; k++) {
            float4 v4 = *(const float4*)&Vs[k][4 * tx];
            float vv[4] = {v4.x, v4.y, v4.z, v4.w};
#pragma unroll
            for (int i = 0; i < 4; i++) {
                float a = PCs[4 * ty + i][k];
#pragma unroll
                for (int j = 0; j < 4; j++)
                    acc[i][j] = fmaf(a, vv[j], acc[i][j]);
            }
        }
        // next iteration's attn_gemm syncthreads protects PCs/Vs reuse
    }

    // Epilogue: reduce l and accOff across the 16 tx-lanes, normalize, store.
#pragma unroll
    for (int i = 0; i < 4; i++) {
        float l = l_part[i], o = off_part[i];
#pragma unroll
        for (int d = 1; d < 16; d <<= 1) {
            l += __shfl_xor_sync(0xffffffffu, l, d);
            o += __shfl_xor_sync(0xffffffffu, o, d);
        }
        float inv = 1.0f / l;
#pragma unroll
        for (int j = 0; j < 4; j++)
            out[(size_t)(r0 + 4 * ty + i) * OUTC + 4 * tx + j] =
                (acc[i][j] + o) * inv;
    }
}

// ---------------------------------------------------------------------------
extern "C" void kernel_launch(void* const* d_in, const int* in_sizes, int n_in,
                              void* d_out, int out_size)
{
    const float* pooled  = (const float*)d_in[0];
    const float* rlat    = (const float*)d_in[1];
    const float* dlat    = (const float*)d_in[2];
    const float* rpos    = (const float*)d_in[3];
    const float* dpos    = (const float*)d_in[4];
    const float* W_rproj = (const float*)d_in[5];
    const float* b_rproj = (const float*)d_in[6];
    const float* W_dproj = (const float*)d_in[7];
    const float* b_dproj = (const float*)d_in[8];
    const float* W_rcon  = (const float*)d_in[9];
    const float* b_rcon  = (const float*)d_in[10];
    const float* W_dcon  = (const float*)d_in[11];
    const float* b_dcon  = (const float*)d_in[12];
    const float* W_roff  = (const float*)d_in[13];
    const float* b_roff  = (const float*)d_in[14];
    const float* W_doff  = (const float*)d_in[15];
    const float* b_doff  = (const float*)d_in[16];
    float* out = (float*)d_out;

    dim3 blk(256);
    // Range features: 13824 rows -> grid.y = 216
    proj_kernel<<<dim3(4, NR / 64), blk>>>(rlat, rpos, W_rproj, b_rproj, 256,   0, 0);
    proj_kernel<<<dim3(2, NR / 64), blk>>>(rlat, rpos, W_rcon,  b_rcon,  128, 256, 0);
    proj_kernel<<<dim3(2, NR / 64), blk>>>(rlat, rpos, W_roff,  b_roff,  128, 384, 0);
    // Domain features: 1728 rows -> grid.y = 27
    proj_kernel<<<dim3(4, ND / 64), blk>>>(dlat, dpos, W_dproj, b_dproj, 256,   0, 1);
    proj_kernel<<<dim3(2, ND / 64), blk>>>(dlat, dpos, W_dcon,  b_dcon,  128, 256, 1);
    proj_kernel<<<dim3(2, ND / 64), blk>>>(dlat, dpos, W_doff,  b_doff,  128, 384, 1);
    // Fused attention
    attn_kernel<<<NR / 64, blk>>>(pooled, out);
}